// round 1
// baseline (speedup 1.0000x reference)
#include <cuda_runtime.h>
#include <cuda_bf16.h>
#include <math_constants.h>

// Problem constants
#define B   2
#define NP  8192
#define C   64
#define M   4096     // NP * 0.5
#define K   128
#define H   128
#define R2  0.04f    // 0.2^2
#define BM  (B*M)    // 8192 centers total

// ---------------- scratch (device globals; no allocation allowed) ----------------
__device__ int   g_flags[B*NP];
__device__ int   g_sidx[BM];                 // sorted FPS indices (local 0..NP-1), per cloud
__device__ float g_Y[(size_t)B*NP*H];        // x @ W1[:C] + b1   (8 MB)
__device__ int   g_nbr[(size_t)BM*K];        // neighbor local indices (4 MB)
__device__ int   g_ncnt[BM];

// ---------------- K0: zero flags ----------------
__global__ void zero_flags_kernel() {
    int i = blockIdx.x * blockDim.x + threadIdx.x;
    if (i < B*NP) g_flags[i] = 0;
}

// ---------------- K1: farthest point sampling ----------------
#define T_FPS 512
#define PTS   (NP / T_FPS)   // 16 points per thread

__global__ void fps_kernel(const float* __restrict__ pos) {
    const int b   = blockIdx.x;
    const int tid = threadIdx.x;
    const int lane = tid & 31, wid = tid >> 5;

    extern __shared__ float sm[];
    float* sx = sm;
    float* sy = sm + NP;
    float* sz = sm + 2 * NP;
    __shared__ float s_far[3];
    __shared__ float s_v[T_FPS/32];
    __shared__ int   s_i[T_FPS/32];

    const float* pb = pos + (size_t)b * NP * 3;
    for (int i = tid; i < NP; i += T_FPS) {
        sx[i] = pb[i*3+0];
        sy[i] = pb[i*3+1];
        sz[i] = pb[i*3+2];
    }
    if (tid == 0) g_flags[b*NP + 0] = 1;   // idx[0] = 0
    __syncthreads();

    // thread-local points (contiguous so smaller thread => smaller index)
    float px[PTS], py[PTS], pz[PTS], mind[PTS];
    const int base = tid * PTS;
    #pragma unroll
    for (int k = 0; k < PTS; k++) {
        px[k] = sx[base+k]; py[k] = sy[base+k]; pz[k] = sz[base+k];
        mind[k] = CUDART_INF_F;
    }
    float fx = sx[0], fy = sy[0], fz = sz[0];

    for (int it = 1; it < M; it++) {
        float bv = -1.0f; int bi = 0;
        #pragma unroll
        for (int k = 0; k < PTS; k++) {
            float dx = px[k] - fx, dy = py[k] - fy, dz = pz[k] - fz;
            float d  = fmaf(dx, dx, fmaf(dy, dy, dz*dz));
            float mm = fminf(mind[k], d);
            mind[k] = mm;
            if (mm > bv) { bv = mm; bi = base + k; }   // strict > : first max wins
        }
        // warp argmax (ties -> smaller index, matching jnp.argmax)
        #pragma unroll
        for (int off = 16; off; off >>= 1) {
            float ov = __shfl_down_sync(0xffffffffu, bv, off);
            int   oi = __shfl_down_sync(0xffffffffu, bi, off);
            if (ov > bv || (ov == bv && oi < bi)) { bv = ov; bi = oi; }
        }
        if (lane == 0) { s_v[wid] = bv; s_i[wid] = bi; }
        __syncthreads();
        if (wid == 0) {
            float v = (lane < T_FPS/32) ? s_v[lane] : -1.0f;
            int   i2 = (lane < T_FPS/32) ? s_i[lane] : 0x7fffffff;
            #pragma unroll
            for (int off = 8; off; off >>= 1) {
                float ov = __shfl_down_sync(0xffffffffu, v, off);
                int   oi = __shfl_down_sync(0xffffffffu, i2, off);
                if (ov > v || (ov == v && oi < i2)) { v = ov; i2 = oi; }
            }
            if (lane == 0) {
                s_far[0] = sx[i2]; s_far[1] = sy[i2]; s_far[2] = sz[i2];
                g_flags[b*NP + i2] = 1;
            }
        }
        __syncthreads();
        fx = s_far[0]; fy = s_far[1]; fz = s_far[2];
    }
}

// ---------------- K2: compaction of flags -> sorted sample indices ----------------
__global__ void compact_kernel() {   // grid = B, block = 32
    const int b = blockIdx.x, lane = threadIdx.x;
    int carry = 0;
    for (int base = 0; base < NP; base += 32) {
        int f = g_flags[b*NP + base + lane];
        unsigned m = __ballot_sync(0xffffffffu, f);
        if (f) {
            int r = __popc(m & ((1u << lane) - 1u));
            g_sidx[b*M + carry + r] = base + lane;
        }
        carry += __popc(m);
    }
}

// ---------------- K3: Y = x @ W1[:C] + b1 ----------------
__global__ void ymat_kernel(const float* __restrict__ x,
                            const float* __restrict__ W1,
                            const float* __restrict__ b1) {
    const int p = blockIdx.x;        // 0 .. B*NP-1
    const int h = threadIdx.x;       // 0 .. H-1
    __shared__ float xv[C];
    if (h < C) xv[h] = x[(size_t)p*C + h];
    __syncthreads();
    float acc = b1[h];
    #pragma unroll
    for (int c = 0; c < C; c++)
        acc = fmaf(xv[c], W1[c*H + h], acc);
    g_Y[(size_t)p*H + h] = acc;
}

// ---------------- K4: radius / top-K neighbor selection ----------------
#define CAP 2048
__global__ void radius_kernel(const float* __restrict__ pos) {  // grid = BM, block = 256
    const int ctr = blockIdx.x;
    const int b   = ctr / M;
    const int ci  = g_sidx[ctr];
    const float* pb = pos + (size_t)b * NP * 3;
    const float cx = pb[ci*3+0], cy = pb[ci*3+1], cz = pb[ci*3+2];

    __shared__ float cd[CAP];
    __shared__ int   cidx[CAP];
    __shared__ int   cnt;
    if (threadIdx.x == 0) cnt = 0;
    __syncthreads();

    for (int i = threadIdx.x; i < NP; i += 256) {
        float dx = pb[i*3+0] - cx, dy = pb[i*3+1] - cy, dz = pb[i*3+2] - cz;
        float d  = fmaf(dx, dx, fmaf(dy, dy, dz*dz));
        if (d <= R2) {
            int s = atomicAdd(&cnt, 1);
            if (s < CAP) { cd[s] = d; cidx[s] = i; }
        }
    }
    __syncthreads();
    int n = min(cnt, CAP);
    if (n <= K) {
        for (int c = threadIdx.x; c < n; c += 256)
            g_nbr[(size_t)ctr*K + c] = cidx[c];
        if (threadIdx.x == 0) g_ncnt[ctr] = n;
    } else {
        // rank selection: keep the K lexicographically-smallest (d2, idx) pairs.
        for (int c = threadIdx.x; c < n; c += 256) {
            float d = cd[c]; int id = cidx[c];
            int r = 0;
            for (int j = 0; j < n; j++) {
                float dj = cd[j];
                r += (dj < d) || (dj == d && cidx[j] < id);
            }
            if (r < K) g_nbr[(size_t)ctr*K + r] = id;
        }
        if (threadIdx.x == 0) g_ncnt[ctr] = K;
    }
}

// ---------------- K5: PointNetConv (h2 matmul + max aggregation) ----------------
__global__ void __launch_bounds__(128)
conv_kernel(const float* __restrict__ pos,
            const float* __restrict__ W1,
            const float* __restrict__ W2,
            const float* __restrict__ b2,
            float* __restrict__ out) {      // grid = BM, block = 128
    const int ctr = blockIdx.x;
    const int b   = ctr / M;
    const int o   = threadIdx.x;

    float wreg[H];
    #pragma unroll
    for (int k = 0; k < H; k++) wreg[k] = W2[k*H + o];

    const int ci = g_sidx[ctr];
    const float* pb = pos + (size_t)b * NP * 3;
    const float cx = pb[ci*3+0], cy = pb[ci*3+1], cz = pb[ci*3+2];
    const float v0 = W1[(C+0)*H + o], v1 = W1[(C+1)*H + o], v2 = W1[(C+2)*H + o];
    const float bias2 = b2[o];

    const int n = g_ncnt[ctr];
    __shared__ __align__(16) float h1[2][H];

    float omax = 0.0f;     // relu output >= 0, n >= 1 always (center is its own neighbor)

    // prefetch neighbor 0
    float yv = 0.f, pjx = 0.f, pjy = 0.f, pjz = 0.f;
    if (n > 0) {
        int j = g_nbr[(size_t)ctr*K + 0];
        yv  = g_Y[(size_t)(b*NP + j)*H + o];
        pjx = pb[j*3+0]; pjy = pb[j*3+1]; pjz = pb[j*3+2];
    }

    for (int nn = 0; nn < n; nn++) {
        float hh = yv;
        hh = fmaf(pjx - cx, v0, hh);
        hh = fmaf(pjy - cy, v1, hh);
        hh = fmaf(pjz - cz, v2, hh);
        hh = fmaxf(hh, 0.0f);
        const int p = nn & 1;
        h1[p][o] = hh;

        // prefetch neighbor nn+1 (overlaps the dot below)
        if (nn + 1 < n) {
            int j = g_nbr[(size_t)ctr*K + nn + 1];
            yv  = g_Y[(size_t)(b*NP + j)*H + o];
            pjx = pb[j*3+0]; pjy = pb[j*3+1]; pjz = pb[j*3+2];
        }
        __syncthreads();

        float a0 = 0.f, a1 = 0.f, a2 = 0.f, a3 = 0.f;
        #pragma unroll
        for (int k = 0; k < H; k += 4) {
            float4 hv = *(const float4*)&h1[p][k];
            a0 = fmaf(hv.x, wreg[k+0], a0);
            a1 = fmaf(hv.y, wreg[k+1], a1);
            a2 = fmaf(hv.z, wreg[k+2], a2);
            a3 = fmaf(hv.w, wreg[k+3], a3);
        }
        float h2 = fmaxf((a0 + a1) + (a2 + a3) + bias2, 0.0f);
        omax = fmaxf(omax, h2);
    }
    out[(size_t)ctr*H + o] = (n > 0) ? omax : 0.0f;
}

// ---------------- K6: pack auxiliary outputs (qpos, batch) if expected ----------------
__global__ void pack_kernel(const float* __restrict__ pos, float* __restrict__ out,
                            int out_size) {
    const int i = blockIdx.x * blockDim.x + threadIdx.x;
    if (i >= BM) return;
    const int b  = i / M;
    const int ci = g_sidx[i];
    const float* pb = pos + (size_t)b * NP * 3;
    const int base_q = BM * H;
    if (out_size >= base_q + BM*3) {
        out[base_q + i*3 + 0] = pb[ci*3+0];
        out[base_q + i*3 + 1] = pb[ci*3+1];
        out[base_q + i*3 + 2] = pb[ci*3+2];
    }
    const int base_b = base_q + BM*3;
    if (out_size >= base_b + BM) {
        out[base_b + i] = (float)b;
    }
}

// ---------------- launch ----------------
extern "C" void kernel_launch(void* const* d_in, const int* in_sizes, int n_in,
                              void* d_out, int out_size) {
    const float* x    = (const float*)d_in[0];
    const float* pos  = (const float*)d_in[1];
    // d_in[2] = batch (int32) — implied by fixed layout, unused
    const float* W1   = (const float*)d_in[3];
    const float* b1   = (const float*)d_in[4];
    const float* W2   = (const float*)d_in[5];
    const float* b2   = (const float*)d_in[6];
    float* out = (float*)d_out;

    // FPS needs 96KB dynamic smem for the pos cache
    const int fps_smem = 3 * NP * (int)sizeof(float);
    cudaFuncSetAttribute(fps_kernel, cudaFuncAttributeMaxDynamicSharedMemorySize, fps_smem);

    zero_flags_kernel<<<(B*NP + 255)/256, 256>>>();
    fps_kernel<<<B, T_FPS, fps_smem>>>(pos);
    compact_kernel<<<B, 32>>>();
    ymat_kernel<<<B*NP, H>>>(x, W1, b1);
    radius_kernel<<<BM, 256>>>(pos);
    conv_kernel<<<BM, H>>>(pos, W1, W2, b2, out);
    pack_kernel<<<(BM + 255)/256, 256>>>(pos, out, out_size);
}

// round 2
// speedup vs baseline: 1.3783x; 1.3783x over previous
#include <cuda_runtime.h>
#include <cuda_bf16.h>
#include <math_constants.h>

// Problem constants
#define B   2
#define NP  8192
#define C   64
#define M   4096     // NP * 0.5
#define K   128
#define H   128
#define R2  0.04f    // 0.2^2
#define BM  (B*M)    // 8192 centers total

// ---------------- scratch (device globals; no allocation allowed) ----------------
__device__ int   g_flags[B*NP];
__device__ int   g_sidx[BM];                 // sorted FPS indices (local 0..NP-1), per cloud
__device__ float g_Y[(size_t)B*NP*H];        // x @ W1[:C] + b1   (8 MB)
__device__ int   g_nbr[(size_t)BM*K];        // neighbor local indices (4 MB)
__device__ int   g_ncnt[BM];

// ---------------- packed f32x2 helpers ----------------
__device__ __forceinline__ unsigned long long pack2f(float lo, float hi) {
    unsigned long long r;
    asm("mov.b64 %0, {%1, %2};" : "=l"(r) : "f"(lo), "f"(hi));
    return r;
}
__device__ __forceinline__ unsigned long long fma2(unsigned long long a,
                                                   unsigned long long b,
                                                   unsigned long long c) {
    unsigned long long d;
    asm("fma.rn.f32x2 %0, %1, %2, %3;" : "=l"(d) : "l"(a), "l"(b), "l"(c));
    return d;
}
__device__ __forceinline__ float2 unpack2f(unsigned long long v) {
    float lo, hi;
    asm("mov.b64 {%0, %1}, %2;" : "=f"(lo), "=f"(hi) : "l"(v));
    return make_float2(lo, hi);
}

// ---------------- K0: zero flags ----------------
__global__ void zero_flags_kernel() {
    int i = blockIdx.x * blockDim.x + threadIdx.x;
    if (i < B*NP) g_flags[i] = 0;
}

// ---------------- K1: farthest point sampling (value-first reduction) ----------------
#define T_FPS 512
#define PTS   (NP / T_FPS)   // 16 points per thread
#define NW    (T_FPS / 32)   // 16 warps

__global__ void fps_kernel(const float* __restrict__ pos) {
    const int b   = blockIdx.x;
    const int tid = threadIdx.x;
    const int lane = tid & 31, wid = tid >> 5;

    extern __shared__ float sm[];
    float* sx = sm;
    float* sy = sm + NP;
    float* sz = sm + 2 * NP;
    __shared__ unsigned s_w[NW];
    __shared__ unsigned s_gmax;
    __shared__ int      s_win;

    const float* pb = pos + (size_t)b * NP * 3;
    for (int i = tid; i < NP; i += T_FPS) {
        sx[i] = pb[i*3+0];
        sy[i] = pb[i*3+1];
        sz[i] = pb[i*3+2];
    }
    if (tid == 0) { g_flags[b*NP + 0] = 1; }   // idx[0] = 0
    __syncthreads();

    // thread-local points (contiguous so index recovery gives original index)
    float px[PTS], py[PTS], pz[PTS], mind[PTS];
    const int base = tid * PTS;
    #pragma unroll
    for (int k = 0; k < PTS; k++) {
        px[k] = sx[base+k]; py[k] = sy[base+k]; pz[k] = sz[base+k];
        mind[k] = CUDART_INF_F;
    }
    float fx = sx[0], fy = sy[0], fz = sz[0];

    for (int it = 1; it < M; it++) {
        // ---- local: update mind, track max VALUE only ----
        float bv = 0.0f;
        #pragma unroll
        for (int k = 0; k < PTS; k++) {
            float dx = px[k] - fx, dy = py[k] - fy, dz = pz[k] - fz;
            float d  = fmaf(dx, dx, fmaf(dy, dy, dz*dz));
            float mm = fminf(mind[k], d);
            mind[k] = mm;
            bv = fmaxf(bv, mm);
        }
        // ---- warp max via redux (d >= 0 -> float bits monotonic as u32) ----
        unsigned wmax = __reduce_max_sync(0xffffffffu, __float_as_uint(bv));
        if (lane == 0) s_w[wid] = wmax;
        __syncthreads();
        if (wid == 0) {
            unsigned v = (lane < NW) ? s_w[lane] : 0u;
            unsigned g = __reduce_max_sync(0xffffffffu, v);
            if (lane == 0) { s_gmax = g; s_win = 0x7fffffff; }
        }
        __syncthreads();
        const float gmax = __uint_as_float(s_gmax);
        // ---- index recovery: only threads holding the max scan their registers ----
        if (bv == gmax) {
            int loc = 0x7fffffff;
            #pragma unroll
            for (int k = 0; k < PTS; k++)
                if (mind[k] == gmax) loc = min(loc, base + k);
            atomicMin(&s_win, loc);   // min index = jnp.argmax first-max semantics
        }
        __syncthreads();
        const int widx = s_win;
        fx = sx[widx]; fy = sy[widx]; fz = sz[widx];
        if (tid == 0) g_flags[b*NP + widx] = 1;
    }
}

// ---------------- K2: compaction of flags -> sorted sample indices ----------------
__global__ void compact_kernel() {   // grid = B, block = 32
    const int b = blockIdx.x, lane = threadIdx.x;
    int carry = 0;
    for (int base = 0; base < NP; base += 32) {
        int f = g_flags[b*NP + base + lane];
        unsigned m = __ballot_sync(0xffffffffu, f);
        if (f) {
            int r = __popc(m & ((1u << lane) - 1u));
            g_sidx[b*M + carry + r] = base + lane;
        }
        carry += __popc(m);
    }
}

// ---------------- K3: Y = x @ W1[:C] + b1 ----------------
__global__ void ymat_kernel(const float* __restrict__ x,
                            const float* __restrict__ W1,
                            const float* __restrict__ b1) {
    const int p = blockIdx.x;        // 0 .. B*NP-1
    const int h = threadIdx.x;       // 0 .. H-1
    __shared__ float xv[C];
    if (h < C) xv[h] = x[(size_t)p*C + h];
    __syncthreads();
    float acc = b1[h];
    #pragma unroll
    for (int c = 0; c < C; c++)
        acc = fmaf(xv[c], W1[c*H + h], acc);
    g_Y[(size_t)p*H + h] = acc;
}

// ---------------- K4: radius / top-K neighbor selection ----------------
#define CAP 2048
__global__ void radius_kernel(const float* __restrict__ pos) {  // grid = BM, block = 256
    const int ctr = blockIdx.x;
    const int b   = ctr / M;
    const int ci  = g_sidx[ctr];
    const float* pb = pos + (size_t)b * NP * 3;
    const float cx = pb[ci*3+0], cy = pb[ci*3+1], cz = pb[ci*3+2];

    __shared__ float cd[CAP];
    __shared__ int   cidx[CAP];
    __shared__ int   cnt;
    if (threadIdx.x == 0) cnt = 0;
    __syncthreads();

    for (int i = threadIdx.x; i < NP; i += 256) {
        float dx = pb[i*3+0] - cx, dy = pb[i*3+1] - cy, dz = pb[i*3+2] - cz;
        float d  = fmaf(dx, dx, fmaf(dy, dy, dz*dz));
        if (d <= R2) {
            int s = atomicAdd(&cnt, 1);
            if (s < CAP) { cd[s] = d; cidx[s] = i; }
        }
    }
    __syncthreads();
    int n = min(cnt, CAP);
    if (n <= K) {
        for (int c = threadIdx.x; c < n; c += 256)
            g_nbr[(size_t)ctr*K + c] = cidx[c];
        if (threadIdx.x == 0) g_ncnt[ctr] = n;
    } else {
        // rank selection: keep the K lexicographically-smallest (d2, idx) pairs.
        for (int c = threadIdx.x; c < n; c += 256) {
            float d = cd[c]; int id = cidx[c];
            int r = 0;
            for (int j = 0; j < n; j++) {
                float dj = cd[j];
                r += (dj < d) || (dj == d && cidx[j] < id);
            }
            if (r < K) g_nbr[(size_t)ctr*K + r] = id;
        }
        if (threadIdx.x == 0) g_ncnt[ctr] = K;
    }
}

// ---------------- K5: PointNetConv (packed f32x2 matmul + max aggregation) ----------------
__global__ void __launch_bounds__(128, 2)
conv_kernel(const float* __restrict__ pos,
            const float* __restrict__ W1,
            const float* __restrict__ W2,
            const float* __restrict__ b2,
            float* __restrict__ out) {      // grid = BM, block = 128
    const int ctr = blockIdx.x;
    const int b   = ctr / M;
    const int o   = threadIdx.x;

    // W2 column o, packed as 64 x f32x2 (pairs over consecutive k)
    unsigned long long wreg[H/2];
    #pragma unroll
    for (int k = 0; k < H; k += 2)
        wreg[k >> 1] = pack2f(W2[k*H + o], W2[(k+1)*H + o]);

    const int ci = g_sidx[ctr];
    const float* pb = pos + (size_t)b * NP * 3;
    const float cx = pb[ci*3+0], cy = pb[ci*3+1], cz = pb[ci*3+2];
    const float v0 = W1[(C+0)*H + o], v1 = W1[(C+1)*H + o], v2 = W1[(C+2)*H + o];
    const float bias2 = b2[o];

    const int n = g_ncnt[ctr];
    __shared__ __align__(16) float h1[2][H];

    float omax = 0.0f;     // relu output >= 0; n >= 1 (center in its own ball)

    // prefetch neighbor 0
    float yv = 0.f, pjx = 0.f, pjy = 0.f, pjz = 0.f;
    if (n > 0) {
        int j = g_nbr[(size_t)ctr*K + 0];
        yv  = g_Y[(size_t)(b*NP + j)*H + o];
        pjx = pb[j*3+0]; pjy = pb[j*3+1]; pjz = pb[j*3+2];
    }

    for (int nn = 0; nn < n; nn++) {
        float hh = yv;
        hh = fmaf(pjx - cx, v0, hh);
        hh = fmaf(pjy - cy, v1, hh);
        hh = fmaf(pjz - cz, v2, hh);
        hh = fmaxf(hh, 0.0f);
        const int p = nn & 1;
        h1[p][o] = hh;

        // prefetch neighbor nn+1 (overlaps the dot below)
        if (nn + 1 < n) {
            int j = g_nbr[(size_t)ctr*K + nn + 1];
            yv  = g_Y[(size_t)(b*NP + j)*H + o];
            pjx = pb[j*3+0]; pjy = pb[j*3+1]; pjz = pb[j*3+2];
        }
        __syncthreads();

        // packed dot: 64 f32x2 FMAs, h1 pairs come free via 128-bit shared loads
        const ulonglong2* hp = (const ulonglong2*)&h1[p][0];
        unsigned long long a0 = 0ull, a1 = 0ull, a2 = 0ull, a3 = 0ull;
        #pragma unroll
        for (int q = 0; q < H/4; q += 2) {
            ulonglong2 hv = hp[q];            // floats 4q .. 4q+3
            a0 = fma2(hv.x, wreg[2*q + 0], a0);
            a1 = fma2(hv.y, wreg[2*q + 1], a1);
            ulonglong2 hw = hp[q + 1];        // floats 4q+4 .. 4q+7
            a2 = fma2(hw.x, wreg[2*q + 2], a2);
            a3 = fma2(hw.y, wreg[2*q + 3], a3);
        }
        float2 f0 = unpack2f(a0), f1 = unpack2f(a1);
        float2 f2 = unpack2f(a2), f3 = unpack2f(a3);
        float s = ((f0.x + f0.y) + (f1.x + f1.y)) + ((f2.x + f2.y) + (f3.x + f3.y));
        float h2 = fmaxf(s + bias2, 0.0f);
        omax = fmaxf(omax, h2);
    }
    out[(size_t)ctr*H + o] = (n > 0) ? omax : 0.0f;
}

// ---------------- K6: pack auxiliary outputs (qpos, batch) if expected ----------------
__global__ void pack_kernel(const float* __restrict__ pos, float* __restrict__ out,
                            int out_size) {
    const int i = blockIdx.x * blockDim.x + threadIdx.x;
    if (i >= BM) return;
    const int b  = i / M;
    const int ci = g_sidx[i];
    const float* pb = pos + (size_t)b * NP * 3;
    const int base_q = BM * H;
    if (out_size >= base_q + BM*3) {
        out[base_q + i*3 + 0] = pb[ci*3+0];
        out[base_q + i*3 + 1] = pb[ci*3+1];
        out[base_q + i*3 + 2] = pb[ci*3+2];
    }
    const int base_b = base_q + BM*3;
    if (out_size >= base_b + BM) {
        out[base_b + i] = (float)b;
    }
}

// ---------------- launch ----------------
extern "C" void kernel_launch(void* const* d_in, const int* in_sizes, int n_in,
                              void* d_out, int out_size) {
    const float* x    = (const float*)d_in[0];
    const float* pos  = (const float*)d_in[1];
    // d_in[2] = batch (int32) — implied by fixed layout, unused
    const float* W1   = (const float*)d_in[3];
    const float* b1   = (const float*)d_in[4];
    const float* W2   = (const float*)d_in[5];
    const float* b2   = (const float*)d_in[6];
    float* out = (float*)d_out;

    // FPS needs 96KB dynamic smem for the pos cache
    const int fps_smem = 3 * NP * (int)sizeof(float);
    cudaFuncSetAttribute(fps_kernel, cudaFuncAttributeMaxDynamicSharedMemorySize, fps_smem);

    zero_flags_kernel<<<(B*NP + 255)/256, 256>>>();
    fps_kernel<<<B, T_FPS, fps_smem>>>(pos);
    compact_kernel<<<B, 32>>>();
    ymat_kernel<<<B*NP, H>>>(x, W1, b1);
    radius_kernel<<<BM, 256>>>(pos);
    conv_kernel<<<BM, H>>>(pos, W1, W2, b2, out);
    pack_kernel<<<(BM + 255)/256, 256>>>(pos, out, out_size);
}

// round 3
// speedup vs baseline: 1.3989x; 1.0149x over previous
#include <cuda_runtime.h>
#include <cuda_bf16.h>
#include <math_constants.h>

// Problem constants
#define B   2
#define NP  8192
#define C   64
#define M   4096     // NP * 0.5
#define K   128
#define H   128
#define R2  0.04f    // 0.2^2
#define BM  (B*M)    // 8192 centers total

// ---------------- scratch (device globals; no allocation allowed) ----------------
__device__ int   g_flags[B*NP];
__device__ int   g_sidx[BM];                 // sorted FPS indices (local 0..NP-1), per cloud
__device__ float g_Y[(size_t)B*NP*H];        // x @ W1[:C] + b1   (8 MB)
__device__ int   g_nbr[(size_t)BM*K];        // neighbor local indices (4 MB)
__device__ int   g_ncnt[BM];

// ---------------- packed f32x2 helpers ----------------
__device__ __forceinline__ unsigned long long pack2f(float lo, float hi) {
    unsigned long long r;
    asm("mov.b64 %0, {%1, %2};" : "=l"(r) : "f"(lo), "f"(hi));
    return r;
}
__device__ __forceinline__ unsigned long long add2(unsigned long long a,
                                                   unsigned long long b) {
    unsigned long long d;
    asm("add.rn.f32x2 %0, %1, %2;" : "=l"(d) : "l"(a), "l"(b));
    return d;
}
__device__ __forceinline__ unsigned long long mul2(unsigned long long a,
                                                   unsigned long long b) {
    unsigned long long d;
    asm("mul.rn.f32x2 %0, %1, %2;" : "=l"(d) : "l"(a), "l"(b));
    return d;
}
__device__ __forceinline__ unsigned long long fma2(unsigned long long a,
                                                   unsigned long long b,
                                                   unsigned long long c) {
    unsigned long long d;
    asm("fma.rn.f32x2 %0, %1, %2, %3;" : "=l"(d) : "l"(a), "l"(b), "l"(c));
    return d;
}
__device__ __forceinline__ float2 unpack2f(unsigned long long v) {
    float lo, hi;
    asm("mov.b64 {%0, %1}, %2;" : "=f"(lo), "=f"(hi) : "l"(v));
    return make_float2(lo, hi);
}

// ---------------- K0: zero flags ----------------
__global__ void zero_flags_kernel() {
    int i = blockIdx.x * blockDim.x + threadIdx.x;
    if (i < B*NP) g_flags[i] = 0;
}

// ---------------- K1: farthest point sampling (f32x2 distances) ----------------
#define T_FPS 512
#define PTS   (NP / T_FPS)   // 16 points per thread
#define PRS   (PTS / 2)      // 8 packed pairs
#define NW    (T_FPS / 32)   // 16 warps

__global__ void fps_kernel(const float* __restrict__ pos) {
    const int b   = blockIdx.x;
    const int tid = threadIdx.x;
    const int lane = tid & 31, wid = tid >> 5;

    extern __shared__ float sm[];
    float* sx = sm;
    float* sy = sm + NP;
    float* sz = sm + 2 * NP;
    __shared__ unsigned s_w[NW];
    __shared__ int      s_win[2];

    const float* pb = pos + (size_t)b * NP * 3;
    for (int i = tid; i < NP; i += T_FPS) {
        sx[i] = pb[i*3+0];
        sy[i] = pb[i*3+1];
        sz[i] = pb[i*3+2];
    }
    if (tid == 0) {
        g_flags[b*NP + 0] = 1;   // idx[0] = 0
        s_win[0] = 0x7fffffff;
        s_win[1] = 0x7fffffff;
    }
    __syncthreads();

    // thread-local points, packed 2 per 64-bit register
    unsigned long long px2[PRS], py2[PRS], pz2[PRS];
    float mind[PTS];
    const int base = tid * PTS;
    #pragma unroll
    for (int k = 0; k < PRS; k++) {
        px2[k] = pack2f(sx[base+2*k], sx[base+2*k+1]);
        py2[k] = pack2f(sy[base+2*k], sy[base+2*k+1]);
        pz2[k] = pack2f(sz[base+2*k], sz[base+2*k+1]);
    }
    #pragma unroll
    for (int k = 0; k < PTS; k++) mind[k] = CUDART_INF_F;

    float fx = sx[0], fy = sy[0], fz = sz[0];

    for (int it = 1; it < M; it++) {
        // ---- local: d = (p-f)^2 in f32x2 (bit-identical per lane to scalar) ----
        const unsigned long long nfx2 = pack2f(-fx, -fx);
        const unsigned long long nfy2 = pack2f(-fy, -fy);
        const unsigned long long nfz2 = pack2f(-fz, -fz);
        float bv0 = 0.0f, bv1 = 0.0f;
        #pragma unroll
        for (int k = 0; k < PRS; k++) {
            unsigned long long dx = add2(px2[k], nfx2);
            unsigned long long dy = add2(py2[k], nfy2);
            unsigned long long dz = add2(pz2[k], nfz2);
            unsigned long long d  = mul2(dz, dz);
            d = fma2(dy, dy, d);
            d = fma2(dx, dx, d);
            float2 df = unpack2f(d);
            float m0 = fminf(mind[2*k+0], df.x); mind[2*k+0] = m0; bv0 = fmaxf(bv0, m0);
            float m1 = fminf(mind[2*k+1], df.y); mind[2*k+1] = m1; bv1 = fmaxf(bv1, m1);
        }
        const float bv = fmaxf(bv0, bv1);

        // ---- warp max via redux (d >= 0 -> float bits monotonic as u32) ----
        unsigned wmax = __reduce_max_sync(0xffffffffu, __float_as_uint(bv));
        if (lane == 0) s_w[wid] = wmax;
        __syncthreads();                                   // bar A

        const int cur = it & 1;
        // every warp computes the block max itself (no second serial reduction stage)
        unsigned g = __reduce_max_sync(0xffffffffu, s_w[lane & (NW-1)]);
        const float gmax = __uint_as_float(g);
        if (tid == 0) s_win[cur ^ 1] = 0x7fffffff;         // reset idle slot (safe between bars)

        // ---- index recovery: only max-holding thread(s) scan their registers ----
        if (bv == gmax) {
            int loc = 0x7fffffff;
            #pragma unroll
            for (int k = 0; k < PTS; k++)
                if (mind[k] == gmax) loc = min(loc, base + k);
            atomicMin(&s_win[cur], loc);  // min index = jnp.argmax first-max semantics
        }
        __syncthreads();                                   // bar B

        const int widx = s_win[cur];
        fx = sx[widx]; fy = sy[widx]; fz = sz[widx];
        if (tid == 0) g_flags[b*NP + widx] = 1;
    }
}

// ---------------- K2: compaction of flags -> sorted sample indices ----------------
__global__ void compact_kernel() {   // grid = B, block = 32
    const int b = blockIdx.x, lane = threadIdx.x;
    int carry = 0;
    for (int base = 0; base < NP; base += 32) {
        int f = g_flags[b*NP + base + lane];
        unsigned m = __ballot_sync(0xffffffffu, f);
        if (f) {
            int r = __popc(m & ((1u << lane) - 1u));
            g_sidx[b*M + carry + r] = base + lane;
        }
        carry += __popc(m);
    }
}

// ---------------- K3: Y = x @ W1[:C] + b1 ----------------
__global__ void ymat_kernel(const float* __restrict__ x,
                            const float* __restrict__ W1,
                            const float* __restrict__ b1) {
    const int p = blockIdx.x;        // 0 .. B*NP-1
    const int h = threadIdx.x;       // 0 .. H-1
    __shared__ float xv[C];
    if (h < C) xv[h] = x[(size_t)p*C + h];
    __syncthreads();
    float acc = b1[h];
    #pragma unroll
    for (int c = 0; c < C; c++)
        acc = fmaf(xv[c], W1[c*H + h], acc);
    g_Y[(size_t)p*H + h] = acc;
}

// ---------------- K4: radius / top-K neighbor selection ----------------
#define CAP 2048
__global__ void radius_kernel(const float* __restrict__ pos) {  // grid = BM, block = 256
    const int ctr = blockIdx.x;
    const int b   = ctr / M;
    const int ci  = g_sidx[ctr];
    const float* pb = pos + (size_t)b * NP * 3;
    const float cx = pb[ci*3+0], cy = pb[ci*3+1], cz = pb[ci*3+2];

    __shared__ float cd[CAP];
    __shared__ int   cidx[CAP];
    __shared__ int   cnt;
    if (threadIdx.x == 0) cnt = 0;
    __syncthreads();

    for (int i = threadIdx.x; i < NP; i += 256) {
        float dx = pb[i*3+0] - cx, dy = pb[i*3+1] - cy, dz = pb[i*3+2] - cz;
        float d  = fmaf(dx, dx, fmaf(dy, dy, dz*dz));
        if (d <= R2) {
            int s = atomicAdd(&cnt, 1);
            if (s < CAP) { cd[s] = d; cidx[s] = i; }
        }
    }
    __syncthreads();
    int n = min(cnt, CAP);
    if (n <= K) {
        for (int c = threadIdx.x; c < n; c += 256)
            g_nbr[(size_t)ctr*K + c] = cidx[c];
        if (threadIdx.x == 0) g_ncnt[ctr] = n;
    } else {
        // rank selection: keep the K lexicographically-smallest (d2, idx) pairs.
        for (int c = threadIdx.x; c < n; c += 256) {
            float d = cd[c]; int id = cidx[c];
            int r = 0;
            for (int j = 0; j < n; j++) {
                float dj = cd[j];
                r += (dj < d) || (dj == d && cidx[j] < id);
            }
            if (r < K) g_nbr[(size_t)ctr*K + r] = id;
        }
        if (threadIdx.x == 0) g_ncnt[ctr] = K;
    }
}

// ---------------- K5: PointNetConv (f32x2 matmul, 4 neighbors per barrier) ----------------
#define GRP 4
__global__ void __launch_bounds__(128, 2)
conv_kernel(const float* __restrict__ pos,
            const float* __restrict__ W1,
            const float* __restrict__ W2,
            const float* __restrict__ b2,
            float* __restrict__ out) {      // grid = BM, block = 128
    const int ctr = blockIdx.x;
    const int b   = ctr / M;
    const int o   = threadIdx.x;

    // W2 column o, packed as 64 x f32x2 (pairs over consecutive k)
    unsigned long long wreg[H/2];
    #pragma unroll
    for (int k = 0; k < H; k += 2)
        wreg[k >> 1] = pack2f(W2[k*H + o], W2[(k+1)*H + o]);

    const int ci = g_sidx[ctr];
    const float* pb = pos + (size_t)b * NP * 3;
    const float cx = pb[ci*3+0], cy = pb[ci*3+1], cz = pb[ci*3+2];
    const float v0 = W1[(C+0)*H + o], v1 = W1[(C+1)*H + o], v2 = W1[(C+2)*H + o];
    const float bias2 = b2[o];

    const int n = g_ncnt[ctr];
    const int* nb = &g_nbr[(size_t)ctr*K];
    __shared__ __align__(16) float h1[2][GRP][H];

    float omax = 0.0f;     // relu output >= 0; n >= 1 (center in its own ball)

    // prologue: prefetch group 0
    float yv[GRP], pjx[GRP], pjy[GRP], pjz[GRP];
    #pragma unroll
    for (int g = 0; g < GRP; g++) {
        if (g < n) {
            int j = nb[g];
            yv[g]  = g_Y[(size_t)(b*NP + j)*H + o];
            pjx[g] = pb[j*3+0]; pjy[g] = pb[j*3+1]; pjz[g] = pb[j*3+2];
        }
    }

    for (int g0 = 0; g0 < n; g0 += GRP) {
        const int buf = (g0 >> 2) & 1;
        #pragma unroll
        for (int g = 0; g < GRP; g++) {
            if (g0 + g < n) {
                float hh = yv[g];
                hh = fmaf(pjx[g] - cx, v0, hh);
                hh = fmaf(pjy[g] - cy, v1, hh);
                hh = fmaf(pjz[g] - cz, v2, hh);
                h1[buf][g][o] = fmaxf(hh, 0.0f);
            }
        }
        // prefetch next group (overlaps barrier + dots)
        #pragma unroll
        for (int g = 0; g < GRP; g++) {
            if (g0 + GRP + g < n) {
                int j = nb[g0 + GRP + g];
                yv[g]  = g_Y[(size_t)(b*NP + j)*H + o];
                pjx[g] = pb[j*3+0]; pjy[g] = pb[j*3+1]; pjz[g] = pb[j*3+2];
            }
        }
        __syncthreads();

        #pragma unroll
        for (int g = 0; g < GRP; g++) {
            if (g0 + g < n) {
                const ulonglong2* hp = (const ulonglong2*)&h1[buf][g][0];
                unsigned long long a0 = 0ull, a1 = 0ull, a2 = 0ull, a3 = 0ull;
                #pragma unroll
                for (int q = 0; q < H/4; q += 2) {
                    ulonglong2 hv = hp[q];            // floats 4q .. 4q+3
                    a0 = fma2(hv.x, wreg[2*q + 0], a0);
                    a1 = fma2(hv.y, wreg[2*q + 1], a1);
                    ulonglong2 hw = hp[q + 1];        // floats 4q+4 .. 4q+7
                    a2 = fma2(hw.x, wreg[2*q + 2], a2);
                    a3 = fma2(hw.y, wreg[2*q + 3], a3);
                }
                float2 f0 = unpack2f(a0), f1 = unpack2f(a1);
                float2 f2 = unpack2f(a2), f3 = unpack2f(a3);
                float s = ((f0.x + f0.y) + (f1.x + f1.y)) + ((f2.x + f2.y) + (f3.x + f3.y));
                omax = fmaxf(omax, fmaxf(s + bias2, 0.0f));
            }
        }
    }
    out[(size_t)ctr*H + o] = (n > 0) ? omax : 0.0f;
}

// ---------------- K6: pack auxiliary outputs (qpos, batch) if expected ----------------
__global__ void pack_kernel(const float* __restrict__ pos, float* __restrict__ out,
                            int out_size) {
    const int i = blockIdx.x * blockDim.x + threadIdx.x;
    if (i >= BM) return;
    const int b  = i / M;
    const int ci = g_sidx[i];
    const float* pb = pos + (size_t)b * NP * 3;
    const int base_q = BM * H;
    if (out_size >= base_q + BM*3) {
        out[base_q + i*3 + 0] = pb[ci*3+0];
        out[base_q + i*3 + 1] = pb[ci*3+1];
        out[base_q + i*3 + 2] = pb[ci*3+2];
    }
    const int base_b = base_q + BM*3;
    if (out_size >= base_b + BM) {
        out[base_b + i] = (float)b;
    }
}

// ---------------- launch ----------------
extern "C" void kernel_launch(void* const* d_in, const int* in_sizes, int n_in,
                              void* d_out, int out_size) {
    const float* x    = (const float*)d_in[0];
    const float* pos  = (const float*)d_in[1];
    // d_in[2] = batch (int32) — implied by fixed layout, unused
    const float* W1   = (const float*)d_in[3];
    const float* b1   = (const float*)d_in[4];
    const float* W2   = (const float*)d_in[5];
    const float* b2   = (const float*)d_in[6];
    float* out = (float*)d_out;

    // FPS needs 96KB dynamic smem for the pos cache
    const int fps_smem = 3 * NP * (int)sizeof(float);
    cudaFuncSetAttribute(fps_kernel, cudaFuncAttributeMaxDynamicSharedMemorySize, fps_smem);

    zero_flags_kernel<<<(B*NP + 255)/256, 256>>>();
    fps_kernel<<<B, T_FPS, fps_smem>>>(pos);
    compact_kernel<<<B, 32>>>();
    ymat_kernel<<<B*NP, H>>>(x, W1, b1);
    radius_kernel<<<BM, 256>>>(pos);
    conv_kernel<<<BM, H>>>(pos, W1, W2, b2, out);
    pack_kernel<<<(BM + 255)/256, 256>>>(pos, out, out_size);
}